// round 6
// baseline (speedup 1.0000x reference)
#include <cuda_runtime.h>

// NeighborSample: x (8,64,64,192) f32 -> out (8*64*64, 5, 5, 192) f32
// out[pix][i][j][k] = x[b][y+i-2][x+j-2][k] (zero-padded)
//
// Smem-tiled: block = (one y row, 16 x-pixels, 64-float channel chunk).
// Input tile (5 rows x 20 cols x 16 float4) loaded once into smem (padding
// materialized as zeros), then each thread writes 25 output positions with
// fully unrolled LDS.128 -> STG.128 and incremental addressing.

#define TX      16u           // pixels per block (x)
#define CCH     16u           // float4 per channel chunk (64 floats)
#define SROWS   5u
#define SCOLS   20u           // TX + 4 halo
#define SSTRIDE 17u           // CCH + 1 pad (bank-conflict avoidance)
#define SMEM_F4 (SROWS * SCOLS * SSTRIDE)   // 1700 float4 = 27.2 KB

__global__ void __launch_bounds__(256, 8) neighbor_sample_tiled(
    const float4* __restrict__ in, float4* __restrict__ out)
{
    __shared__ float4 s[SMEM_F4];

    // block decode: bx = ((b*64 + y)*4 + xt)*3 + cc
    unsigned bx = blockIdx.x;
    unsigned cc = bx % 3u;
    unsigned t1 = bx / 3u;
    unsigned xt = t1 & 3u;
    unsigned t2 = t1 >> 2;
    unsigned y  = t2 & 63u;
    unsigned b  = t2 >> 6;
    unsigned x0 = xt * TX;
    unsigned c0 = cc * CCH;
    unsigned tid = threadIdx.x;

    // ---- load phase: 5 x 20 x 16 float4 = 1600 elements, zeros in halo ----
    for (unsigned l = tid; l < SROWS * SCOLS * CCH; l += 256u) {
        unsigned k4  = l & 15u;
        unsigned cl  = l >> 4;        // 0..99
        unsigned col = cl % SCOLS;
        unsigned row = cl / SCOLS;
        int gx = (int)(x0 + col) - 2;
        int gy = (int)(y + row) - 2;
        float4 v = make_float4(0.f, 0.f, 0.f, 0.f);
        if ((unsigned)gx < 64u && (unsigned)gy < 64u) {
            unsigned src = ((((b << 6) + (unsigned)gy) << 6) | (unsigned)gx) * 48u + c0 + k4;
            v = __ldg(&in[src]);
        }
        s[(row * SCOLS + col) * SSTRIDE + k4] = v;
    }
    __syncthreads();

    // ---- store phase: warp = 2 contiguous 256B runs -> perfect 4-line stores ----
    unsigned k4  = tid & 15u;
    unsigned px  = tid >> 4;                       // 0..15
    unsigned pix = (((b << 6) + y) << 6) + x0 + px;
    unsigned o   = pix * 1200u + c0 + k4;          // (pix*25*48) float4
    unsigned sb  = px * SSTRIDE + k4;

    #pragma unroll
    for (unsigned i = 0; i < 5u; i++) {
        #pragma unroll
        for (unsigned j = 0; j < 5u; j++) {
            float4 v = s[sb + (i * SCOLS + j) * SSTRIDE];
            __stcs(&out[o], v);   // streaming: don't pollute L2 with the 629MB write stream
            o += 48u;
        }
    }
}

extern "C" void kernel_launch(void* const* d_in, const int* in_sizes, int n_in,
                              void* d_out, int out_size)
{
    const float4* in  = (const float4*)d_in[0];
    float4*       out = (float4*)d_out;
    // grid = b(8) * y(64) * xtiles(4) * cchunks(3) = 6144 blocks
    neighbor_sample_tiled<<<6144, 256>>>(in, out);
}